// round 9
// baseline (speedup 1.0000x reference)
#include <cuda_runtime.h>
#include <math.h>

#define N_NODES 100000
#define N_EDGES 1600000
#define NUM_G   4096
#define EPSV    1e-5f
#define SCAN_B  1024
#define SCAN_NB ((N_NODES + SCAN_B - 1) / SCAN_B)

// ---------------- scratch (__device__ globals: allocation-free) ----------------
__device__ __align__(16) float  d_eemb[N_EDGES * 16];   // edge embeddings (CSR order)
__device__ __align__(16) float  d_P[N_NODES * 256];     // per-node Wa·h (dst|src halves)
__device__ __align__(16) float  d_h[N_NODES * 64];      // embedded node features
__device__ __align__(16) float  d_sum[N_NODES * 64];    // conv output [N,H2]
__device__ __align__(16) float  d_agg[N_NODES * 128];   // aggregated relu(hid) [N,H1]
__device__ int    d_degi[N_NODES];
__device__ int    d_rowptr[N_NODES + 1];
__device__ int    d_cursor[N_NODES];
__device__ int    d_srcs[N_EDGES];
__device__ int    d_bsum[SCAN_NB];
__device__ double d_stats[128];
__device__ float  d_pool[NUM_G * 16];
__device__ float  d_pcnt[NUM_G];

// ---------------- f32x2 packed helpers (Blackwell) ----------------
__device__ __forceinline__ unsigned long long pk2(float a, float b) {
    unsigned long long r;
    asm("mov.b64 %0, {%1,%2};" : "=l"(r) : "f"(a), "f"(b));
    return r;
}
__device__ __forceinline__ void upk2(unsigned long long v, float& a, float& b) {
    asm("mov.b64 {%0,%1}, %2;" : "=f"(a), "=f"(b) : "l"(v));
}
__device__ __forceinline__ void fma2(unsigned long long& d, unsigned long long a, unsigned long long b) {
    asm("fma.rn.f32x2 %0, %1, %2, %0;" : "+l"(d) : "l"(a), "l"(b));
}

// ---------------- CSR build ----------------
__global__ void k_hist(const int* __restrict__ dstp, int* __restrict__ degi) {
    int e = blockIdx.x * blockDim.x + threadIdx.x;
    if (e < N_EDGES) atomicAdd(&degi[dstp[e]], 1);
}

__global__ void __launch_bounds__(SCAN_B) k_scan1(const int* __restrict__ degi,
                                                  int* __restrict__ rowptr,
                                                  int* __restrict__ bsum) {
    __shared__ int sh[SCAN_B];
    int i = blockIdx.x * SCAN_B + threadIdx.x;
    sh[threadIdx.x] = (i < N_NODES) ? degi[i] : 0;
    __syncthreads();
    for (int off = 1; off < SCAN_B; off <<= 1) {
        int t = (threadIdx.x >= off) ? sh[threadIdx.x - off] : 0;
        __syncthreads();
        sh[threadIdx.x] += t;
        __syncthreads();
    }
    if (i < N_NODES) rowptr[i + 1] = sh[threadIdx.x];
    if (threadIdx.x == SCAN_B - 1) bsum[blockIdx.x] = sh[threadIdx.x];
}

// parallel exclusive scan over SCAN_NB block sums (single block)
__global__ void __launch_bounds__(128) k_scan2(int* __restrict__ bsum) {
    __shared__ int sh[128];
    int t = threadIdx.x;
    int v = (t < SCAN_NB) ? bsum[t] : 0;
    sh[t] = v;
    __syncthreads();
    #pragma unroll
    for (int off = 1; off < 128; off <<= 1) {
        int u = (t >= off) ? sh[t - off] : 0;
        __syncthreads();
        sh[t] += u;
        __syncthreads();
    }
    if (t < SCAN_NB) bsum[t] = sh[t] - v;   // exclusive
}

__global__ void k_scan3(int* __restrict__ rowptr, const int* __restrict__ bsum) {
    int i = blockIdx.x * blockDim.x + threadIdx.x;
    if (i == 0) rowptr[0] = 0;
    if (i < N_NODES) rowptr[i + 1] += bsum[i / SCAN_B];
}

// ---------------- CSR scatter fused with edge embedding ----------------
__global__ void k_scatter_emb(const float* __restrict__ ea, const float* __restrict__ We,
                              const float* __restrict__ be,
                              const int* __restrict__ srcp, const int* __restrict__ dstp,
                              const int* __restrict__ rowptr, int* __restrict__ cursor,
                              int* __restrict__ srcs, float* __restrict__ eemb) {
    __shared__ float WeS[128];
    __shared__ float beS[16];
    int tid = threadIdx.x;
    if (tid < 128) WeS[tid] = We[tid];
    if (tid < 16)  beS[tid] = be[tid];
    __syncthreads();
    int e = blockIdx.x * blockDim.x + tid;
    if (e >= N_EDGES) return;
    int d = dstp[e];
    int p = rowptr[d] + atomicAdd(&cursor[d], 1);
    srcs[p] = srcp[e];
    float4 v0 = *(const float4*)&ea[(size_t)e * 8];
    float4 v1 = *(const float4*)&ea[(size_t)e * 8 + 4];
    float a[8] = {v0.x, v0.y, v0.z, v0.w, v1.x, v1.y, v1.z, v1.w};
    float o[16];
    #pragma unroll
    for (int j = 0; j < 16; j++) o[j] = beS[j];
    #pragma unroll
    for (int k = 0; k < 8; k++)
        #pragma unroll
        for (int j = 0; j < 16; j++) o[j] += a[k] * WeS[k * 16 + j];
    #pragma unroll
    for (int j = 0; j < 16; j++) o[j] = fmaxf(o[j], 0.0f);
    float4* op = (float4*)&eemb[(size_t)p * 16];
    op[0] = make_float4(o[0], o[1], o[2], o[3]);
    op[1] = make_float4(o[4], o[5], o[6], o[7]);
    op[2] = make_float4(o[8], o[9], o[10], o[11]);
    op[3] = make_float4(o[12], o[13], o[14], o[15]);
}

// ---------------- node GEMM (chunked weight layout), f32x2, fused BN/bias modes ----------------
// MODE 0: plain A, plain out.  MODE 1: plain A, out=relu(out+bias).  MODE 2: A=BN+relu(A), plain out.
template<int K, int J, int H1, int MODE>
__global__ void __launch_bounds__(256) k_gemm_node(const float* __restrict__ A,
                                                   const float* __restrict__ W,
                                                   const float* __restrict__ bias,
                                                   const double* __restrict__ stats,
                                                   const float* __restrict__ gbn,
                                                   const float* __restrict__ bbn,
                                                   float* __restrict__ C) {
    __shared__ float As[64 * K];
    __shared__ float Ws[K * 64];
    __shared__ float scS[MODE == 2 ? K : 1];
    __shared__ float shS[MODE == 2 ? K : 1];
    int tid = threadIdx.x;
    int n0  = blockIdx.x * 64;
    int cj0 = blockIdx.y * 64;
    if (MODE == 2) {
        if (tid < K) {
            float mu  = (float)(stats[tid] / (double)N_NODES);
            float var = (float)(stats[64 + tid] / (double)N_NODES) - mu * mu;
            float rs = rsqrtf(fmaxf(var, 0.0f) + EPSV);
            float sc = rs * gbn[tid];
            scS[tid] = sc;
            shS[tid] = bbn[tid] - mu * sc;
        }
        __syncthreads();
    }
    for (int idx = tid; idx < K * 64; idx += 256) {
        int k = idx / 64, jj = idx % 64;
        int c = cj0 + jj;
        Ws[idx] = W[((c / H1) * K + k) * H1 + (c % H1)];
    }
    for (int idx = tid; idx < 64 * K; idx += 256) {
        int nl = idx / K, k = idx % K;
        int n = n0 + nl;
        float v = (n < N_NODES) ? A[(size_t)n * K + k] : 0.0f;
        if (MODE == 2) v = fmaxf(fmaf(v, scS[k], shS[k]), 0.0f);
        As[idx] = v;
    }
    __syncthreads();
    int ty = tid / 16, tx = tid % 16;
    unsigned long long acc2[4][2];
    #pragma unroll
    for (int i = 0; i < 4; i++) { acc2[i][0] = 0ull; acc2[i][1] = 0ull; }
    #pragma unroll 4
    for (int k = 0; k < K; k++) {
        ulonglong2 w = *(const ulonglong2*)&Ws[k * 64 + tx * 4];
        #pragma unroll
        for (int i = 0; i < 4; i++) {
            float av = As[(ty + 16 * i) * K + k];
            unsigned long long a2 = pk2(av, av);
            fma2(acc2[i][0], a2, w.x);
            fma2(acc2[i][1], a2, w.y);
        }
    }
    #pragma unroll
    for (int i = 0; i < 4; i++) {
        int n = n0 + ty + 16 * i;
        if (n < N_NODES) {
            float v0, v1, v2, v3;
            upk2(acc2[i][0], v0, v1);
            upk2(acc2[i][1], v2, v3);
            if (MODE == 1) {
                int c = cj0 + tx * 4;
                v0 = fmaxf(v0 + bias[c + 0], 0.0f);
                v1 = fmaxf(v1 + bias[c + 1], 0.0f);
                v2 = fmaxf(v2 + bias[c + 2], 0.0f);
                v3 = fmaxf(v3 + bias[c + 3], 0.0f);
            }
            float4 r; r.x = v0; r.y = v1; r.z = v2; r.w = v3;
            *(float4*)&C[(size_t)n * J + cj0 + tx * 4] = r;
        }
    }
}

// ---------------- conv aggregate: warp per (node, channel-block) ----------------
// agg[n][ch] = (1/deg)*sum_e relu(P[n][ch] + P[src][H1+ch] + (e@Wae)[ch] + ba[ch])
// Latency structure: src indices are CSR-contiguous -> one coalesced LDG per 32
// edges into a lane register, per-edge index via shfl (off the memory critical
// path). P[src] gather is software-pipelined at depth 2 (issue at i, use at i+2).
template<int H1, int CB>
__global__ void __launch_bounds__(256) k_conv_agg(
    const float* __restrict__ P, const float* __restrict__ eemb,
    const int* __restrict__ srcs, const int* __restrict__ rowptr,
    const float* __restrict__ Wae, const float* __restrict__ ba,
    float* __restrict__ agg, double* __restrict__ stats)
{
    if (blockIdx.x == 0 && threadIdx.x < 128) stats[threadIdx.x] = 0.0;
    constexpr int C  = H1 / 32 / CB;   // 2 (conv1,conv2) or 1 (conv3)
    constexpr int RS = 2 * H1;
    constexpr int HB = H1 / CB;        // channels per warp
    static_assert(C == 1 || C == 2, "C must be 1 or 2");
    const int lane = threadIdx.x & 31;
    const int w0 = blockIdx.x * 8 + (threadIdx.x >> 5);
    const int nwarps = gridDim.x * 8;
    const int cb = w0 % CB;
    const int ch = cb * HB + lane * C;
    const float* __restrict__ Psrc = P + H1 + ch;   // src-half base for my channels

    unsigned long long wae2[C][8];
    #pragma unroll
    for (int c = 0; c < C; c++)
        #pragma unroll
        for (int k2 = 0; k2 < 8; k2++)
            wae2[c][k2] = pk2(Wae[(2 * k2) * H1 + ch + c], Wae[(2 * k2 + 1) * H1 + ch + c]);
    float bav[C];
    #pragma unroll
    for (int c = 0; c < C; c++) bav[c] = ba[ch + c];

    for (int u = w0; u < N_NODES * CB; u += nwarps) {
        const int n = u / CB;
        const int r0 = rowptr[n];
        const int deg = rowptr[n + 1] - r0;
        float pdb[C], acc[C];
        if constexpr (C == 2) {
            float2 v = __ldcs((const float2*)(P + (size_t)n * RS + ch));
            pdb[0] = v.x + bav[0]; pdb[1] = v.y + bav[1];
        } else {
            pdb[0] = __ldcs(P + (size_t)n * RS + ch) + bav[0];
        }
        #pragma unroll
        for (int c = 0; c < C; c++) acc[c] = 0.0f;

        if (deg > 0) {
            // window 0 of src indices (coalesced; per-edge access via shfl)
            int wb = 0;
            int sreg = (lane < deg) ? __ldg(srcs + r0 + lane) : 0;
            float ps_cur[C], ps_nxt[C];
            {
                int s0 = __shfl_sync(0xffffffffu, sreg, 0);
                if constexpr (C == 2) {
                    float2 v = __ldg((const float2*)(Psrc + (size_t)s0 * RS));
                    ps_cur[0] = v.x; ps_cur[1] = v.y;
                } else {
                    ps_cur[0] = __ldg(Psrc + (size_t)s0 * RS);
                }
            }
            if (deg > 1) {
                int s1 = __shfl_sync(0xffffffffu, sreg, 1);
                if constexpr (C == 2) {
                    float2 v = __ldg((const float2*)(Psrc + (size_t)s1 * RS));
                    ps_nxt[0] = v.x; ps_nxt[1] = v.y;
                } else {
                    ps_nxt[0] = __ldg(Psrc + (size_t)s1 * RS);
                }
            }
            for (int i = 0; i < deg; i++) {
                // eemb row: CSR-contiguous, uniform across warp (L1-resident)
                const float4* ep = (const float4*)(eemb + (size_t)(r0 + i) * 16);
                float4 f0 = __ldcs(ep + 0), f1 = __ldcs(ep + 1);
                float4 f2 = __ldcs(ep + 2), f3 = __ldcs(ep + 3);
                unsigned long long ev[8];
                ev[0] = pk2(f0.x, f0.y); ev[1] = pk2(f0.z, f0.w);
                ev[2] = pk2(f1.x, f1.y); ev[3] = pk2(f1.z, f1.w);
                ev[4] = pk2(f2.x, f2.y); ev[5] = pk2(f2.z, f2.w);
                ev[6] = pk2(f3.x, f3.y); ev[7] = pk2(f3.z, f3.w);
                #pragma unroll
                for (int c = 0; c < C; c++) {
                    unsigned long long z0 = 0ull, z1 = 0ull;
                    fma2(z0, ev[0], wae2[c][0]); fma2(z1, ev[1], wae2[c][1]);
                    fma2(z0, ev[2], wae2[c][2]); fma2(z1, ev[3], wae2[c][3]);
                    fma2(z0, ev[4], wae2[c][4]); fma2(z1, ev[5], wae2[c][5]);
                    fma2(z0, ev[6], wae2[c][6]); fma2(z1, ev[7], wae2[c][7]);
                    float a, b, x, y;
                    upk2(z0, a, b); upk2(z1, x, y);
                    float hid = pdb[c] + ps_cur[c] + ((a + b) + (x + y));
                    acc[c] += fmaxf(hid, 0.0f);
                }
                // rotate pipeline and issue gather for edge i+2
                #pragma unroll
                for (int c = 0; c < C; c++) ps_cur[c] = ps_nxt[c];
                int j = i + 2;
                if (j < deg) {
                    if (j - wb == 32) {   // next index window
                        wb += 32;
                        sreg = (wb + lane < deg) ? __ldg(srcs + r0 + wb + lane) : 0;
                    }
                    int sj = __shfl_sync(0xffffffffu, sreg, j - wb);
                    if constexpr (C == 2) {
                        float2 v = __ldg((const float2*)(Psrc + (size_t)sj * RS));
                        ps_nxt[0] = v.x; ps_nxt[1] = v.y;
                    } else {
                        ps_nxt[0] = __ldg(Psrc + (size_t)sj * RS);
                    }
                }
            }
        }
        const float inv = (deg > 0) ? (1.0f / (float)deg) : 0.0f;
        float* op = agg + (size_t)n * H1 + ch;
        if constexpr (C == 2) {
            float2 r; r.x = acc[0] * inv; r.y = acc[1] * inv;
            *(float2*)op = r;
        } else {
            *op = acc[0] * inv;
        }
    }
}

// ---------------- GEMM: Cout[N,COLS] = A[N,K] @ W[K,COLS] (+bias if deg>0), fused BN stats ----------------
template<int K, int COLS>
__global__ void __launch_bounds__(256) k_gemm2(const float* __restrict__ A,
                                               const float* __restrict__ W,
                                               const float* __restrict__ bias,
                                               const int* __restrict__ rowptr,
                                               float* __restrict__ Cout,
                                               double* __restrict__ stats) {
    constexpr int KT   = 32;
    constexpr int TX   = COLS / 4;
    constexpr int TY   = 256 / TX;
    constexpr int ROWS = 64;
    constexpr int R    = ROWS / TY;
    __shared__ float As[ROWS * K];
    __shared__ float Ws[KT * COLS];
    __shared__ float sS[TY * COLS];
    __shared__ float qS[TY * COLS];
    const int tid = threadIdx.x;
    const int n0 = blockIdx.x * ROWS;
    for (int idx = tid; idx < ROWS * K; idx += 256) {
        int nl = idx / K, k = idx % K;
        int n = n0 + nl;
        As[idx] = (n < N_NODES) ? A[(size_t)n * K + k] : 0.0f;
    }
    const int ty = tid / TX, tx = tid % TX;
    unsigned long long acc2[R][2];
    #pragma unroll
    for (int i = 0; i < R; i++) { acc2[i][0] = 0ull; acc2[i][1] = 0ull; }
    for (int kt = 0; kt < K; kt += KT) {
        __syncthreads();
        for (int idx = tid; idx < KT * COLS; idx += 256)
            Ws[idx] = W[(size_t)(kt + idx / COLS) * COLS + (idx % COLS)];
        __syncthreads();
        #pragma unroll 4
        for (int k = 0; k < KT; k++) {
            ulonglong2 w = *(const ulonglong2*)&Ws[k * COLS + tx * 4];
            #pragma unroll
            for (int i = 0; i < R; i++) {
                float av = As[(ty + TY * i) * K + kt + k];
                unsigned long long a2 = pk2(av, av);
                fma2(acc2[i][0], a2, w.x);
                fma2(acc2[i][1], a2, w.y);
            }
        }
    }
    float b0 = bias[tx * 4 + 0], b1 = bias[tx * 4 + 1];
    float b2 = bias[tx * 4 + 2], b3 = bias[tx * 4 + 3];
    float s[4] = {0, 0, 0, 0}, q[4] = {0, 0, 0, 0};
    #pragma unroll
    for (int i = 0; i < R; i++) {
        int n = n0 + ty + TY * i;
        if (n < N_NODES) {
            float v0, v1, v2, v3;
            upk2(acc2[i][0], v0, v1);
            upk2(acc2[i][1], v2, v3);
            if (rowptr[n + 1] > rowptr[n]) { v0 += b0; v1 += b1; v2 += b2; v3 += b3; }
            float4 r; r.x = v0; r.y = v1; r.z = v2; r.w = v3;
            *(float4*)&Cout[(size_t)n * COLS + tx * 4] = r;
            s[0] += v0; s[1] += v1; s[2] += v2; s[3] += v3;
            q[0] += v0 * v0; q[1] += v1 * v1; q[2] += v2 * v2; q[3] += v3 * v3;
        }
    }
    __syncthreads();
    #pragma unroll
    for (int j = 0; j < 4; j++) {
        sS[ty * COLS + tx * 4 + j] = s[j];
        qS[ty * COLS + tx * 4 + j] = q[j];
    }
    __syncthreads();
    if (tid < COLS) {
        float ss = 0.0f, qq = 0.0f;
        #pragma unroll 4
        for (int t = 0; t < TY; t++) { ss += sS[t * COLS + tid]; qq += qS[t * COLS + tid]; }
        atomicAdd(&stats[tid], (double)ss);
        atomicAdd(&stats[64 + tid], (double)qq);
    }
}

// ---------------- global mean pool with fused BN+relu ----------------
__global__ void k_pool_bn(const float* __restrict__ sum, const double* __restrict__ stats,
                          const float* __restrict__ g, const float* __restrict__ b,
                          const int* __restrict__ batch,
                          float* __restrict__ pool, float* __restrict__ pcnt) {
    __shared__ float scS[16], shS[16];
    int tid = threadIdx.x;
    if (tid < 16) {
        float mu  = (float)(stats[tid] / (double)N_NODES);
        float var = (float)(stats[64 + tid] / (double)N_NODES) - mu * mu;
        float rs = rsqrtf(fmaxf(var, 0.0f) + EPSV);
        float sc = rs * g[tid];
        scS[tid] = sc;
        shS[tid] = b[tid] - mu * sc;
    }
    __syncthreads();
    int i = blockIdx.x * blockDim.x + tid;
    if (i >= N_NODES * 16) return;
    int n = i >> 4, f = i & 15;
    float v = fmaxf(fmaf(sum[i], scS[f], shS[f]), 0.0f);
    int gr = batch[n];
    atomicAdd(&pool[gr * 16 + f], v);
    if (f == 0) atomicAdd(&pcnt[gr], 1.0f);
}

// ---------------- final fc + sigmoid ----------------
__global__ void k_final(const float* __restrict__ pool, const float* __restrict__ pcnt,
                        const float* __restrict__ Wfc, const float* __restrict__ bfc,
                        float* __restrict__ out) {
    int i = blockIdx.x * blockDim.x + threadIdx.x;
    if (i >= NUM_G * 12) return;
    int g = i / 12, t = i % 12;
    float inv = 1.0f / fmaxf(pcnt[g], 1.0f);
    float acc = bfc[t];
    #pragma unroll
    for (int f = 0; f < 16; f++) acc += pool[g * 16 + f] * inv * Wfc[f * 12 + t];
    out[i] = 1.0f / (1.0f + expf(-acc));
}

// ---------------- launcher ----------------
extern "C" void kernel_launch(void* const* d_in, const int* in_sizes, int n_in,
                              void* d_out, int out_size) {
    const float* x     = (const float*)d_in[0];
    const float* ea    = (const float*)d_in[1];
    const int*   ei    = (const int*)d_in[2];
    const int*   batch = (const int*)d_in[3];
    int wo = (in_sizes[4] == 2048) ? 4 : 5;
    const float* Wn  = (const float*)d_in[wo + 0];
    const float* bn_ = (const float*)d_in[wo + 1];
    const float* We  = (const float*)d_in[wo + 2];
    const float* be_ = (const float*)d_in[wo + 3];
    const float* W1a = (const float*)d_in[wo + 4];
    const float* b1a = (const float*)d_in[wo + 5];
    const float* W1b = (const float*)d_in[wo + 6];
    const float* b1b = (const float*)d_in[wo + 7];
    const float* W2a = (const float*)d_in[wo + 8];
    const float* b2a = (const float*)d_in[wo + 9];
    const float* W2b = (const float*)d_in[wo + 10];
    const float* b2b = (const float*)d_in[wo + 11];
    const float* W3a = (const float*)d_in[wo + 12];
    const float* b3a = (const float*)d_in[wo + 13];
    const float* W3b = (const float*)d_in[wo + 14];
    const float* b3b = (const float*)d_in[wo + 15];
    const float* g1  = (const float*)d_in[wo + 16];
    const float* be1 = (const float*)d_in[wo + 17];
    const float* g2  = (const float*)d_in[wo + 18];
    const float* be2 = (const float*)d_in[wo + 19];
    const float* g3  = (const float*)d_in[wo + 20];
    const float* be3 = (const float*)d_in[wo + 21];
    const float* Wfc = (const float*)d_in[wo + 22];
    const float* bfc = (const float*)d_in[wo + 23];
    float* out = (float*)d_out;

    const int* srcp = ei;
    const int* dstp = ei + N_EDGES;

    void *p_eemb, *p_P, *p_h, *p_sum, *p_agg, *p_degi, *p_rowptr, *p_cursor,
         *p_srcs, *p_bsum, *p_stats, *p_pool, *p_pcnt;
    cudaGetSymbolAddress(&p_eemb, d_eemb);
    cudaGetSymbolAddress(&p_P, d_P);
    cudaGetSymbolAddress(&p_h, d_h);
    cudaGetSymbolAddress(&p_sum, d_sum);
    cudaGetSymbolAddress(&p_agg, d_agg);
    cudaGetSymbolAddress(&p_degi, d_degi);
    cudaGetSymbolAddress(&p_rowptr, d_rowptr);
    cudaGetSymbolAddress(&p_cursor, d_cursor);
    cudaGetSymbolAddress(&p_srcs, d_srcs);
    cudaGetSymbolAddress(&p_bsum, d_bsum);
    cudaGetSymbolAddress(&p_stats, d_stats);
    cudaGetSymbolAddress(&p_pool, d_pool);
    cudaGetSymbolAddress(&p_pcnt, d_pcnt);
    float*  eemb   = (float*)p_eemb;
    float*  P      = (float*)p_P;
    float*  h      = (float*)p_h;
    float*  sum    = (float*)p_sum;
    float*  agg    = (float*)p_agg;
    int*    degi   = (int*)p_degi;
    int*    rowptr = (int*)p_rowptr;
    int*    cursor = (int*)p_cursor;
    int*    srcs   = (int*)p_srcs;
    int*    bsum   = (int*)p_bsum;
    double* stats  = (double*)p_stats;
    float*  pool   = (float*)p_pool;
    float*  pcnt   = (float*)p_pcnt;

    const int NB64 = (N_NODES + 63) / 64;    // 1563
    const int EB   = (N_EDGES + 255) / 256;  // 6250

    // ---- CSR build + fused edge embedding ----
    cudaMemsetAsync(p_degi, 0, N_NODES * sizeof(int));
    cudaMemsetAsync(p_cursor, 0, N_NODES * sizeof(int));
    cudaMemsetAsync(p_pool, 0, NUM_G * 16 * sizeof(float));
    cudaMemsetAsync(p_pcnt, 0, NUM_G * sizeof(float));
    k_hist<<<EB, 256>>>(dstp, degi);
    k_scan1<<<SCAN_NB, SCAN_B>>>(degi, rowptr, bsum);
    k_scan2<<<1, 128>>>(bsum);
    k_scan3<<<(N_NODES + 255) / 256, 256>>>(rowptr, bsum);
    k_scatter_emb<<<EB, 256>>>(ea, We, be_, srcp, dstp, rowptr, cursor, srcs, eemb);

    // ---- node embedding ----
    k_gemm_node<32, 64, 64, 1><<<dim3(NB64, 1), 256>>>(x, Wn, bn_, nullptr, nullptr, nullptr, h);

    // ---- conv1: 64 -> (144->128->64) ----
    k_gemm_node<64, 256, 128, 0><<<dim3(NB64, 4), 256>>>(h, W1a, nullptr, nullptr, nullptr, nullptr, P);
    k_conv_agg<128, 2><<<2048, 256>>>(P, eemb, srcs, rowptr, W1a + 128 * 128, b1a, agg, stats);
    k_gemm2<128, 64><<<NB64, 256>>>(agg, W1b, b1b, rowptr, sum, stats);

    // ---- conv2: 64 -> (144->64->32), BN1 fused into A-load ----
    k_gemm_node<64, 128, 64, 2><<<dim3(NB64, 2), 256>>>(sum, W2a, nullptr, stats, g1, be1, P);
    k_conv_agg<64, 1><<<2048, 256>>>(P, eemb, srcs, rowptr, W2a + 128 * 64, b2a, agg, stats);
    k_gemm2<64, 32><<<NB64, 256>>>(agg, W2b, b2b, rowptr, sum, stats);

    // ---- conv3: 32 -> (80->32->16), BN2 fused into A-load ----
    k_gemm_node<32, 64, 32, 2><<<dim3(NB64, 1), 256>>>(sum, W3a, nullptr, stats, g2, be2, P);
    k_conv_agg<32, 1><<<2048, 256>>>(P, eemb, srcs, rowptr, W3a + 64 * 32, b3a, agg, stats);
    k_gemm2<32, 16><<<NB64, 256>>>(agg, W3b, b3b, rowptr, sum, stats);

    // ---- pool (BN3 fused) + fc + sigmoid ----
    k_pool_bn<<<(N_NODES * 16 + 255) / 256, 256>>>(sum, stats, g3, be3, batch, pool, pcnt);
    k_final<<<(NUM_G * 12 + 255) / 256, 256>>>(pool, pcnt, Wfc, bfc, out);
}

// round 10
// speedup vs baseline: 1.0256x; 1.0256x over previous
#include <cuda_runtime.h>
#include <math.h>

#define N_NODES 100000
#define N_EDGES 1600000
#define NUM_G   4096
#define EPSV    1e-5f
#define SCAN_B  1024
#define SCAN_NB ((N_NODES + SCAN_B - 1) / SCAN_B)

// ---------------- scratch (__device__ globals: allocation-free) ----------------
__device__ __align__(16) float  d_eemb[N_EDGES * 16];   // edge embeddings (CSR order)
__device__ __align__(16) float  d_P[N_NODES * 256];     // per-node Wa·h (dst|src halves)
__device__ __align__(16) float  d_h[N_NODES * 64];      // embedded node features
__device__ __align__(16) float  d_sum[N_NODES * 64];    // conv output [N,H2]
__device__ __align__(16) float  d_agg[N_NODES * 128];   // aggregated relu(hid) [N,H1]
__device__ int    d_degi[N_NODES];
__device__ int    d_rowptr[N_NODES + 1];
__device__ int    d_cursor[N_NODES];
__device__ int    d_srcs[N_EDGES];
__device__ int    d_bsum[SCAN_NB];
__device__ double d_stats[128];
__device__ float  d_pool[NUM_G * 16];
__device__ float  d_pcnt[NUM_G];

// ---------------- f32x2 packed helpers (Blackwell) ----------------
__device__ __forceinline__ unsigned long long pk2(float a, float b) {
    unsigned long long r;
    asm("mov.b64 %0, {%1,%2};" : "=l"(r) : "f"(a), "f"(b));
    return r;
}
__device__ __forceinline__ void upk2(unsigned long long v, float& a, float& b) {
    asm("mov.b64 {%0,%1}, %2;" : "=f"(a), "=f"(b) : "l"(v));
}
__device__ __forceinline__ void fma2(unsigned long long& d, unsigned long long a, unsigned long long b) {
    asm("fma.rn.f32x2 %0, %1, %2, %0;" : "+l"(d) : "l"(a), "l"(b));
}

// ---------------- CSR build ----------------
__global__ void k_hist(const int* __restrict__ dstp, int* __restrict__ degi) {
    int e = blockIdx.x * blockDim.x + threadIdx.x;
    if (e < N_EDGES) atomicAdd(&degi[dstp[e]], 1);
}

__global__ void __launch_bounds__(SCAN_B) k_scan1(const int* __restrict__ degi,
                                                  int* __restrict__ rowptr,
                                                  int* __restrict__ bsum) {
    __shared__ int sh[SCAN_B];
    int i = blockIdx.x * SCAN_B + threadIdx.x;
    sh[threadIdx.x] = (i < N_NODES) ? degi[i] : 0;
    __syncthreads();
    for (int off = 1; off < SCAN_B; off <<= 1) {
        int t = (threadIdx.x >= off) ? sh[threadIdx.x - off] : 0;
        __syncthreads();
        sh[threadIdx.x] += t;
        __syncthreads();
    }
    if (i < N_NODES) rowptr[i + 1] = sh[threadIdx.x];
    if (threadIdx.x == SCAN_B - 1) bsum[blockIdx.x] = sh[threadIdx.x];
}

__global__ void __launch_bounds__(128) k_scan2(int* __restrict__ bsum) {
    __shared__ int sh[128];
    int t = threadIdx.x;
    int v = (t < SCAN_NB) ? bsum[t] : 0;
    sh[t] = v;
    __syncthreads();
    #pragma unroll
    for (int off = 1; off < 128; off <<= 1) {
        int u = (t >= off) ? sh[t - off] : 0;
        __syncthreads();
        sh[t] += u;
        __syncthreads();
    }
    if (t < SCAN_NB) bsum[t] = sh[t] - v;   // exclusive
}

__global__ void k_scan3(int* __restrict__ rowptr, const int* __restrict__ bsum) {
    int i = blockIdx.x * blockDim.x + threadIdx.x;
    if (i == 0) rowptr[0] = 0;
    if (i < N_NODES) rowptr[i + 1] += bsum[i / SCAN_B];
}

// ---------------- CSR scatter fused with edge embedding ----------------
__global__ void k_scatter_emb(const float* __restrict__ ea, const float* __restrict__ We,
                              const float* __restrict__ be,
                              const int* __restrict__ srcp, const int* __restrict__ dstp,
                              const int* __restrict__ rowptr, int* __restrict__ cursor,
                              int* __restrict__ srcs, float* __restrict__ eemb) {
    __shared__ float WeS[128];
    __shared__ float beS[16];
    int tid = threadIdx.x;
    if (tid < 128) WeS[tid] = We[tid];
    if (tid < 16)  beS[tid] = be[tid];
    __syncthreads();
    int e = blockIdx.x * blockDim.x + tid;
    if (e >= N_EDGES) return;
    int d = dstp[e];
    int p = rowptr[d] + atomicAdd(&cursor[d], 1);
    srcs[p] = srcp[e];
    float4 v0 = *(const float4*)&ea[(size_t)e * 8];
    float4 v1 = *(const float4*)&ea[(size_t)e * 8 + 4];
    float a[8] = {v0.x, v0.y, v0.z, v0.w, v1.x, v1.y, v1.z, v1.w};
    float o[16];
    #pragma unroll
    for (int j = 0; j < 16; j++) o[j] = beS[j];
    #pragma unroll
    for (int k = 0; k < 8; k++)
        #pragma unroll
        for (int j = 0; j < 16; j++) o[j] += a[k] * WeS[k * 16 + j];
    #pragma unroll
    for (int j = 0; j < 16; j++) o[j] = fmaxf(o[j], 0.0f);
    float4* op = (float4*)&eemb[(size_t)p * 16];
    op[0] = make_float4(o[0], o[1], o[2], o[3]);
    op[1] = make_float4(o[4], o[5], o[6], o[7]);
    op[2] = make_float4(o[8], o[9], o[10], o[11]);
    op[3] = make_float4(o[12], o[13], o[14], o[15]);
}

// ---------------- node GEMM (chunked weight layout), f32x2, fused BN/bias modes ----------------
// MODE 0: plain A, plain out.  MODE 1: plain A, out=relu(out+bias).  MODE 2: A=BN+relu(A), plain out.
template<int K, int J, int H1, int MODE>
__global__ void __launch_bounds__(256) k_gemm_node(const float* __restrict__ A,
                                                   const float* __restrict__ W,
                                                   const float* __restrict__ bias,
                                                   const double* __restrict__ stats,
                                                   const float* __restrict__ gbn,
                                                   const float* __restrict__ bbn,
                                                   float* __restrict__ C) {
    __shared__ float As[64 * K];
    __shared__ float Ws[K * 64];
    __shared__ float scS[MODE == 2 ? K : 1];
    __shared__ float shS[MODE == 2 ? K : 1];
    int tid = threadIdx.x;
    int n0  = blockIdx.x * 64;
    int cj0 = blockIdx.y * 64;
    if (MODE == 2) {
        if (tid < K) {
            float mu  = (float)(stats[tid] / (double)N_NODES);
            float var = (float)(stats[64 + tid] / (double)N_NODES) - mu * mu;
            float rs = rsqrtf(fmaxf(var, 0.0f) + EPSV);
            float sc = rs * gbn[tid];
            scS[tid] = sc;
            shS[tid] = bbn[tid] - mu * sc;
        }
        __syncthreads();
    }
    for (int idx = tid; idx < K * 64; idx += 256) {
        int k = idx / 64, jj = idx % 64;
        int c = cj0 + jj;
        Ws[idx] = W[((c / H1) * K + k) * H1 + (c % H1)];
    }
    for (int idx = tid; idx < 64 * K; idx += 256) {
        int nl = idx / K, k = idx % K;
        int n = n0 + nl;
        float v = (n < N_NODES) ? A[(size_t)n * K + k] : 0.0f;
        if (MODE == 2) v = fmaxf(fmaf(v, scS[k], shS[k]), 0.0f);
        As[idx] = v;
    }
    __syncthreads();
    int ty = tid / 16, tx = tid % 16;
    unsigned long long acc2[4][2];
    #pragma unroll
    for (int i = 0; i < 4; i++) { acc2[i][0] = 0ull; acc2[i][1] = 0ull; }
    #pragma unroll 4
    for (int k = 0; k < K; k++) {
        ulonglong2 w = *(const ulonglong2*)&Ws[k * 64 + tx * 4];
        #pragma unroll
        for (int i = 0; i < 4; i++) {
            float av = As[(ty + 16 * i) * K + k];
            unsigned long long a2 = pk2(av, av);
            fma2(acc2[i][0], a2, w.x);
            fma2(acc2[i][1], a2, w.y);
        }
    }
    #pragma unroll
    for (int i = 0; i < 4; i++) {
        int n = n0 + ty + 16 * i;
        if (n < N_NODES) {
            float v0, v1, v2, v3;
            upk2(acc2[i][0], v0, v1);
            upk2(acc2[i][1], v2, v3);
            if (MODE == 1) {
                int c = cj0 + tx * 4;
                v0 = fmaxf(v0 + bias[c + 0], 0.0f);
                v1 = fmaxf(v1 + bias[c + 1], 0.0f);
                v2 = fmaxf(v2 + bias[c + 2], 0.0f);
                v3 = fmaxf(v3 + bias[c + 3], 0.0f);
            }
            float4 r; r.x = v0; r.y = v1; r.z = v2; r.w = v3;
            *(float4*)&C[(size_t)n * J + cj0 + tx * 4] = r;
        }
    }
}

// ---------------- conv aggregate (R8-proven): warp per (node, channel-block) ----------------
template<int H1, int CB>
__global__ void __launch_bounds__(256) k_conv_agg(
    const float* __restrict__ P, const float* __restrict__ eemb,
    const int* __restrict__ srcs, const int* __restrict__ rowptr,
    const float* __restrict__ Wae, const float* __restrict__ ba,
    float* __restrict__ agg, double* __restrict__ stats)
{
    if (blockIdx.x == 0 && threadIdx.x < 128) stats[threadIdx.x] = 0.0;
    constexpr int C  = H1 / 32 / CB;   // 2 (conv1,conv2) or 1 (conv3)
    constexpr int RS = 2 * H1;
    constexpr int HB = H1 / CB;
    static_assert(C == 1 || C == 2, "C must be 1 or 2");
    const int lane = threadIdx.x & 31;
    const int w0 = blockIdx.x * 8 + (threadIdx.x >> 5);
    const int nwarps = gridDim.x * 8;
    const int cb = w0 % CB;
    const int ch = cb * HB + lane * C;

    unsigned long long wae2[C][8];
    #pragma unroll
    for (int c = 0; c < C; c++)
        #pragma unroll
        for (int k2 = 0; k2 < 8; k2++)
            wae2[c][k2] = pk2(Wae[(2 * k2) * H1 + ch + c], Wae[(2 * k2 + 1) * H1 + ch + c]);
    float bav[C];
    #pragma unroll
    for (int c = 0; c < C; c++) bav[c] = ba[ch + c];

    for (int u = w0; u < N_NODES * CB; u += nwarps) {
        const int n = u / CB;
        const int r0 = rowptr[n], r1 = rowptr[n + 1];
        const int deg = r1 - r0;
        float pdb[C], acc[C];
        if constexpr (C == 2) {
            float2 v = __ldcs((const float2*)(P + (size_t)n * RS + ch));
            pdb[0] = v.x + bav[0]; pdb[1] = v.y + bav[1];
        } else {
            pdb[0] = __ldcs(P + (size_t)n * RS + ch) + bav[0];
        }
        #pragma unroll
        for (int c = 0; c < C; c++) acc[c] = 0.0f;

        float ps[C];
        if (deg > 0) {
            const int s = srcs[r0];
            if constexpr (C == 2) {
                float2 v = __ldg((const float2*)(P + (size_t)s * RS + H1 + ch));
                ps[0] = v.x; ps[1] = v.y;
            } else {
                ps[0] = __ldg(P + (size_t)s * RS + H1 + ch);
            }
        }
        for (int i = 0; i < deg; i++) {
            float psn[C];
            const bool more = (i + 1 < deg);
            if (more) {  // prefetch next P[src] gather (the only long-latency load)
                const int s = srcs[r0 + i + 1];
                if constexpr (C == 2) {
                    float2 v = __ldg((const float2*)(P + (size_t)s * RS + H1 + ch));
                    psn[0] = v.x; psn[1] = v.y;
                } else {
                    psn[0] = __ldg(P + (size_t)s * RS + H1 + ch);
                }
            }
            const float4* ep = (const float4*)(eemb + (size_t)(r0 + i) * 16);
            float4 f0 = __ldcs(ep + 0), f1 = __ldcs(ep + 1);
            float4 f2 = __ldcs(ep + 2), f3 = __ldcs(ep + 3);
            unsigned long long ev[8];
            ev[0] = pk2(f0.x, f0.y); ev[1] = pk2(f0.z, f0.w);
            ev[2] = pk2(f1.x, f1.y); ev[3] = pk2(f1.z, f1.w);
            ev[4] = pk2(f2.x, f2.y); ev[5] = pk2(f2.z, f2.w);
            ev[6] = pk2(f3.x, f3.y); ev[7] = pk2(f3.z, f3.w);
            #pragma unroll
            for (int c = 0; c < C; c++) {
                unsigned long long z0 = 0ull, z1 = 0ull;
                fma2(z0, ev[0], wae2[c][0]); fma2(z1, ev[1], wae2[c][1]);
                fma2(z0, ev[2], wae2[c][2]); fma2(z1, ev[3], wae2[c][3]);
                fma2(z0, ev[4], wae2[c][4]); fma2(z1, ev[5], wae2[c][5]);
                fma2(z0, ev[6], wae2[c][6]); fma2(z1, ev[7], wae2[c][7]);
                float a, b, x, y;
                upk2(z0, a, b); upk2(z1, x, y);
                float hid = pdb[c] + ps[c] + ((a + b) + (x + y));
                acc[c] += fmaxf(hid, 0.0f);
            }
            if (more) {
                #pragma unroll
                for (int c = 0; c < C; c++) ps[c] = psn[c];
            }
        }
        const float inv = (deg > 0) ? (1.0f / (float)deg) : 0.0f;
        float* op = agg + (size_t)n * H1 + ch;
        if constexpr (C == 2) {
            float2 r; r.x = acc[0] * inv; r.y = acc[1] * inv;
            *(float2*)op = r;
        } else {
            *op = acc[0] * inv;
        }
    }
}

// ---------------- GEMM: Cout[N,COLS] = A[N,K] @ W[K,COLS] (+bias if deg>0), fused BN stats ----------------
template<int K, int COLS>
__global__ void __launch_bounds__(256) k_gemm2(const float* __restrict__ A,
                                               const float* __restrict__ W,
                                               const float* __restrict__ bias,
                                               const int* __restrict__ rowptr,
                                               float* __restrict__ Cout,
                                               double* __restrict__ stats) {
    constexpr int KT   = 32;
    constexpr int TX   = COLS / 4;
    constexpr int TY   = 256 / TX;
    constexpr int ROWS = 64;
    constexpr int R    = ROWS / TY;
    __shared__ float As[ROWS * K];
    __shared__ float Ws[KT * COLS];
    __shared__ float sS[TY * COLS];
    __shared__ float qS[TY * COLS];
    const int tid = threadIdx.x;
    const int n0 = blockIdx.x * ROWS;
    for (int idx = tid; idx < ROWS * K; idx += 256) {
        int nl = idx / K, k = idx % K;
        int n = n0 + nl;
        As[idx] = (n < N_NODES) ? A[(size_t)n * K + k] : 0.0f;
    }
    const int ty = tid / TX, tx = tid % TX;
    unsigned long long acc2[R][2];
    #pragma unroll
    for (int i = 0; i < R; i++) { acc2[i][0] = 0ull; acc2[i][1] = 0ull; }
    for (int kt = 0; kt < K; kt += KT) {
        __syncthreads();
        for (int idx = tid; idx < KT * COLS; idx += 256)
            Ws[idx] = W[(size_t)(kt + idx / COLS) * COLS + (idx % COLS)];
        __syncthreads();
        #pragma unroll 4
        for (int k = 0; k < KT; k++) {
            ulonglong2 w = *(const ulonglong2*)&Ws[k * COLS + tx * 4];
            #pragma unroll
            for (int i = 0; i < R; i++) {
                float av = As[(ty + TY * i) * K + kt + k];
                unsigned long long a2 = pk2(av, av);
                fma2(acc2[i][0], a2, w.x);
                fma2(acc2[i][1], a2, w.y);
            }
        }
    }
    float b0 = bias[tx * 4 + 0], b1 = bias[tx * 4 + 1];
    float b2 = bias[tx * 4 + 2], b3 = bias[tx * 4 + 3];
    float s[4] = {0, 0, 0, 0}, q[4] = {0, 0, 0, 0};
    #pragma unroll
    for (int i = 0; i < R; i++) {
        int n = n0 + ty + TY * i;
        if (n < N_NODES) {
            float v0, v1, v2, v3;
            upk2(acc2[i][0], v0, v1);
            upk2(acc2[i][1], v2, v3);
            if (rowptr[n + 1] > rowptr[n]) { v0 += b0; v1 += b1; v2 += b2; v3 += b3; }
            float4 r; r.x = v0; r.y = v1; r.z = v2; r.w = v3;
            *(float4*)&Cout[(size_t)n * COLS + tx * 4] = r;
            s[0] += v0; s[1] += v1; s[2] += v2; s[3] += v3;
            q[0] += v0 * v0; q[1] += v1 * v1; q[2] += v2 * v2; q[3] += v3 * v3;
        }
    }
    __syncthreads();
    #pragma unroll
    for (int j = 0; j < 4; j++) {
        sS[ty * COLS + tx * 4 + j] = s[j];
        qS[ty * COLS + tx * 4 + j] = q[j];
    }
    __syncthreads();
    if (tid < COLS) {
        float ss = 0.0f, qq = 0.0f;
        #pragma unroll 4
        for (int t = 0; t < TY; t++) { ss += sS[t * COLS + tid]; qq += qS[t * COLS + tid]; }
        atomicAdd(&stats[tid], (double)ss);
        atomicAdd(&stats[64 + tid], (double)qq);
    }
}

// ---------------- global mean pool with fused BN+relu ----------------
__global__ void k_pool_bn(const float* __restrict__ sum, const double* __restrict__ stats,
                          const float* __restrict__ g, const float* __restrict__ b,
                          const int* __restrict__ batch,
                          float* __restrict__ pool, float* __restrict__ pcnt) {
    __shared__ float scS[16], shS[16];
    int tid = threadIdx.x;
    if (tid < 16) {
        float mu  = (float)(stats[tid] / (double)N_NODES);
        float var = (float)(stats[64 + tid] / (double)N_NODES) - mu * mu;
        float rs = rsqrtf(fmaxf(var, 0.0f) + EPSV);
        float sc = rs * g[tid];
        scS[tid] = sc;
        shS[tid] = b[tid] - mu * sc;
    }
    __syncthreads();
    int i = blockIdx.x * blockDim.x + tid;
    if (i >= N_NODES * 16) return;
    int n = i >> 4, f = i & 15;
    float v = fmaxf(fmaf(sum[i], scS[f], shS[f]), 0.0f);
    int gr = batch[n];
    atomicAdd(&pool[gr * 16 + f], v);
    if (f == 0) atomicAdd(&pcnt[gr], 1.0f);
}

// ---------------- final fc + sigmoid ----------------
__global__ void k_final(const float* __restrict__ pool, const float* __restrict__ pcnt,
                        const float* __restrict__ Wfc, const float* __restrict__ bfc,
                        float* __restrict__ out) {
    int i = blockIdx.x * blockDim.x + threadIdx.x;
    if (i >= NUM_G * 12) return;
    int g = i / 12, t = i % 12;
    float inv = 1.0f / fmaxf(pcnt[g], 1.0f);
    float acc = bfc[t];
    #pragma unroll
    for (int f = 0; f < 16; f++) acc += pool[g * 16 + f] * inv * Wfc[f * 12 + t];
    out[i] = 1.0f / (1.0f + expf(-acc));
}

// ---------------- launcher ----------------
extern "C" void kernel_launch(void* const* d_in, const int* in_sizes, int n_in,
                              void* d_out, int out_size) {
    const float* x     = (const float*)d_in[0];
    const float* ea    = (const float*)d_in[1];
    const int*   ei    = (const int*)d_in[2];
    const int*   batch = (const int*)d_in[3];
    int wo = (in_sizes[4] == 2048) ? 4 : 5;
    const float* Wn  = (const float*)d_in[wo + 0];
    const float* bn_ = (const float*)d_in[wo + 1];
    const float* We  = (const float*)d_in[wo + 2];
    const float* be_ = (const float*)d_in[wo + 3];
    const float* W1a = (const float*)d_in[wo + 4];
    const float* b1a = (const float*)d_in[wo + 5];
    const float* W1b = (const float*)d_in[wo + 6];
    const float* b1b = (const float*)d_in[wo + 7];
    const float* W2a = (const float*)d_in[wo + 8];
    const float* b2a = (const float*)d_in[wo + 9];
    const float* W2b = (const float*)d_in[wo + 10];
    const float* b2b = (const float*)d_in[wo + 11];
    const float* W3a = (const float*)d_in[wo + 12];
    const float* b3a = (const float*)d_in[wo + 13];
    const float* W3b = (const float*)d_in[wo + 14];
    const float* b3b = (const float*)d_in[wo + 15];
    const float* g1  = (const float*)d_in[wo + 16];
    const float* be1 = (const float*)d_in[wo + 17];
    const float* g2  = (const float*)d_in[wo + 18];
    const float* be2 = (const float*)d_in[wo + 19];
    const float* g3  = (const float*)d_in[wo + 20];
    const float* be3 = (const float*)d_in[wo + 21];
    const float* Wfc = (const float*)d_in[wo + 22];
    const float* bfc = (const float*)d_in[wo + 23];
    float* out = (float*)d_out;

    const int* srcp = ei;
    const int* dstp = ei + N_EDGES;

    void *p_eemb, *p_P, *p_h, *p_sum, *p_agg, *p_degi, *p_rowptr, *p_cursor,
         *p_srcs, *p_bsum, *p_stats, *p_pool, *p_pcnt;
    cudaGetSymbolAddress(&p_eemb, d_eemb);
    cudaGetSymbolAddress(&p_P, d_P);
    cudaGetSymbolAddress(&p_h, d_h);
    cudaGetSymbolAddress(&p_sum, d_sum);
    cudaGetSymbolAddress(&p_agg, d_agg);
    cudaGetSymbolAddress(&p_degi, d_degi);
    cudaGetSymbolAddress(&p_rowptr, d_rowptr);
    cudaGetSymbolAddress(&p_cursor, d_cursor);
    cudaGetSymbolAddress(&p_srcs, d_srcs);
    cudaGetSymbolAddress(&p_bsum, d_bsum);
    cudaGetSymbolAddress(&p_stats, d_stats);
    cudaGetSymbolAddress(&p_pool, d_pool);
    cudaGetSymbolAddress(&p_pcnt, d_pcnt);
    float*  eemb   = (float*)p_eemb;
    float*  P      = (float*)p_P;
    float*  h      = (float*)p_h;
    float*  sum    = (float*)p_sum;
    float*  agg    = (float*)p_agg;
    int*    degi   = (int*)p_degi;
    int*    rowptr = (int*)p_rowptr;
    int*    cursor = (int*)p_cursor;
    int*    srcs   = (int*)p_srcs;
    int*    bsum   = (int*)p_bsum;
    double* stats  = (double*)p_stats;
    float*  pool   = (float*)p_pool;
    float*  pcnt   = (float*)p_pcnt;

    // one-time host-side stream/event creation (outside capture: first call is
    // the uncaptured correctness run; captured calls reuse the same handles and
    // emit identical work every time)
    static cudaStream_t sB = nullptr;
    static cudaEvent_t evF = nullptr, evB = nullptr;
    if (sB == nullptr) {
        cudaStreamCreateWithFlags(&sB, cudaStreamNonBlocking);
        cudaEventCreateWithFlags(&evF, cudaEventDisableTiming);
        cudaEventCreateWithFlags(&evB, cudaEventDisableTiming);
    }

    const int NB64 = (N_NODES + 63) / 64;    // 1563
    const int EB   = (N_EDGES + 255) / 256;  // 6250

    // ---- fork: branch B (node embedding + conv1 P-GEMM) runs concurrently
    //      with branch A (CSR build + scatter/edge-embedding) ----
    cudaEventRecord(evF, 0);
    cudaStreamWaitEvent(sB, evF, 0);
    k_gemm_node<32, 64, 64, 1><<<dim3(NB64, 1), 256, 0, sB>>>(x, Wn, bn_, nullptr, nullptr, nullptr, h);
    k_gemm_node<64, 256, 128, 0><<<dim3(NB64, 4), 256, 0, sB>>>(h, W1a, nullptr, nullptr, nullptr, nullptr, P);
    cudaEventRecord(evB, sB);

    // ---- branch A on the main stream ----
    cudaMemsetAsync(p_degi, 0, N_NODES * sizeof(int));
    cudaMemsetAsync(p_cursor, 0, N_NODES * sizeof(int));
    cudaMemsetAsync(p_pool, 0, NUM_G * 16 * sizeof(float));
    cudaMemsetAsync(p_pcnt, 0, NUM_G * sizeof(float));
    k_hist<<<EB, 256>>>(dstp, degi);
    k_scan1<<<SCAN_NB, SCAN_B>>>(degi, rowptr, bsum);
    k_scan2<<<1, 128>>>(bsum);
    k_scan3<<<(N_NODES + 255) / 256, 256>>>(rowptr, bsum);
    k_scatter_emb<<<EB, 256>>>(ea, We, be_, srcp, dstp, rowptr, cursor, srcs, eemb);

    // ---- join ----
    cudaStreamWaitEvent(0, evB, 0);

    // ---- conv1: 64 -> (144->128->64) ----
    k_conv_agg<128, 2><<<2048, 256>>>(P, eemb, srcs, rowptr, W1a + 128 * 128, b1a, agg, stats);
    k_gemm2<128, 64><<<NB64, 256>>>(agg, W1b, b1b, rowptr, sum, stats);

    // ---- conv2: 64 -> (144->64->32), BN1 fused into A-load ----
    k_gemm_node<64, 128, 64, 2><<<dim3(NB64, 2), 256>>>(sum, W2a, nullptr, stats, g1, be1, P);
    k_conv_agg<64, 1><<<2048, 256>>>(P, eemb, srcs, rowptr, W2a + 128 * 64, b2a, agg, stats);
    k_gemm2<64, 32><<<NB64, 256>>>(agg, W2b, b2b, rowptr, sum, stats);

    // ---- conv3: 32 -> (80->32->16), BN2 fused into A-load ----
    k_gemm_node<32, 64, 32, 2><<<dim3(NB64, 1), 256>>>(sum, W3a, nullptr, stats, g2, be2, P);
    k_conv_agg<32, 1><<<2048, 256>>>(P, eemb, srcs, rowptr, W3a + 64 * 32, b3a, agg, stats);
    k_gemm2<32, 16><<<NB64, 256>>>(agg, W3b, b3b, rowptr, sum, stats);

    // ---- pool (BN3 fused) + fc + sigmoid ----
    k_pool_bn<<<(N_NODES * 16 + 255) / 256, 256>>>(sum, stats, g3, be3, batch, pool, pcnt);
    k_final<<<(NUM_G * 12 + 255) / 256, 256>>>(pool, pcnt, Wfc, bfc, out);
}